// round 2
// baseline (speedup 1.0000x reference)
#include <cuda_runtime.h>
#include <math.h>

#define Bq   64
#define Lq   256
#define DINq 768
#define Hq   64
#define Eq   8
#define NT   (Bq * Lq)

typedef unsigned long long ull;

// ---------------- device scratch ----------------
__device__ float g_mean[NT];
__device__ int   g_e1[Bq], g_e2[Bq];
__device__ float g_g1[Bq], g_g2[Bq];
__device__ float g_gbias[Bq * Hq];
__device__ float g_Wcomb[Bq * DINq * Hq];
__device__ float g_Y  [NT * Hq];
__device__ float g_SH [NT * Hq];
__device__ float g_RGB[NT * Hq];
__device__ float g_T  [NT * 2 * Hq];

// ---------------- packed f32x2 helpers ----------------
__device__ __forceinline__ ull fma2(ull a, ull b, ull c) {
    ull d;
    asm("fma.rn.f32x2 %0, %1, %2, %3;" : "=l"(d) : "l"(a), "l"(b), "l"(c));
    return d;
}
__device__ __forceinline__ ull pk2(float x) {
    ull r; unsigned u = __float_as_uint(x);
    asm("mov.b64 %0, {%1, %1};" : "=l"(r) : "r"(u));
    return r;
}
__device__ __forceinline__ float2 unpk(ull v) {
    unsigned lo, hi;
    asm("mov.b64 {%0, %1}, %2;" : "=r"(lo), "=r"(hi) : "l"(v));
    return make_float2(__uint_as_float(lo), __uint_as_float(hi));
}

__device__ __forceinline__ float gelu1(float x) {
    return 0.5f * x * (1.0f + erff(x * 0.7071067811865475f));
}
__device__ __forceinline__ float4 f4add(float4 a, float4 b) {
    return make_float4(a.x + b.x, a.y + b.y, a.z + b.z, a.w + b.w);
}
__device__ __forceinline__ float4 f4mul(float4 a, float4 b) {
    return make_float4(a.x * b.x, a.y * b.y, a.z * b.z, a.w * b.w);
}
__device__ __forceinline__ float4 gelu4(float4 a) {
    return make_float4(gelu1(a.x), gelu1(a.y), gelu1(a.z), gelu1(a.w));
}

// ---------------- K0: row mean ----------------
__global__ void k_mean(const float* __restrict__ dte) {
    int w = threadIdx.x >> 5, lane = threadIdx.x & 31;
    int row = blockIdx.x * 8 + w;
    const float* p = dte + (size_t)row * DINq + lane;
    float s = 0.0f;
#pragma unroll
    for (int k = 0; k < DINq / 32; k++) s += p[k * 32];
#pragma unroll
    for (int o = 16; o; o >>= 1) s += __shfl_xor_sync(0xffffffffu, s, o);
    if (lane == 0) g_mean[row] = s * (1.0f / (float)DINq);
}

// ---------------- K1: gating ----------------
__global__ void k_gate(const float* __restrict__ w_gate,
                       const float* __restrict__ b_exp,
                       float* __restrict__ d_out, int loss_idx) {
    __shared__ float s_imp[Eq];
    __shared__ float s_load[Eq];
    int b = threadIdx.x;
    if (b < Eq) { s_imp[b] = 0.0f; s_load[b] = 0.0f; }
    __syncthreads();

    float lg[Eq];
#pragma unroll
    for (int e = 0; e < Eq; e++) lg[e] = 0.0f;
    for (int l = 0; l < Lq; l++) {
        float m = g_mean[b * Lq + l];
#pragma unroll
        for (int e = 0; e < Eq; e++) lg[e] += m * w_gate[l * Eq + e];
    }
    int e1 = 0;
    for (int e = 1; e < Eq; e++) if (lg[e] > lg[e1]) e1 = e;
    int e2 = -1;
    for (int e = 0; e < Eq; e++) {
        if (e == e1) continue;
        if (e2 < 0 || lg[e] > lg[e2]) e2 = e;
    }
    float v1 = lg[e1], v2 = lg[e2];
    float ex = expf(v2 - v1);
    float den = 1.0f / (1.0f + ex);
    float g1 = den, g2 = ex * den;

    g_e1[b] = e1; g_e2[b] = e2; g_g1[b] = g1; g_g2[b] = g2;
    for (int h = 0; h < Hq; h++)
        g_gbias[b * Hq + h] = g1 * b_exp[e1 * Hq + h] + g2 * b_exp[e2 * Hq + h];

    atomicAdd(&s_imp[e1], g1);
    atomicAdd(&s_imp[e2], g2);
    atomicAdd(&s_load[e1], 1.0f);
    atomicAdd(&s_load[e2], 1.0f);
    __syncthreads();

    if (b == 0) {
        float m1 = 0.0f, m2 = 0.0f;
        for (int e = 0; e < Eq; e++) { m1 += s_imp[e]; m2 += s_load[e]; }
        m1 *= (1.0f / Eq); m2 *= (1.0f / Eq);
        float var1 = 0.0f, var2 = 0.0f;
        for (int e = 0; e < Eq; e++) {
            float d1 = s_imp[e] - m1;  var1 += d1 * d1;
            float d2 = s_load[e] - m2; var2 += d2 * d2;
        }
        var1 *= (1.0f / (Eq - 1)); var2 *= (1.0f / (Eq - 1));
        d_out[loss_idx] = 0.01f * (var1 / (m1 * m1 + 1e-10f) +
                                   var2 / (m2 * m2 + 1e-10f));
    }
}

// ---------------- K2: combined expert weight ----------------
__global__ void k_wcomb(const float* __restrict__ W_exp) {
    int b = blockIdx.y;
    int idx = blockIdx.x * 256 + threadIdx.x;
    float g1 = g_g1[b], g2 = g_g2[b];
    int e1 = g_e1[b], e2 = g_e2[b];
    const float4* w1 = (const float4*)W_exp + (size_t)e1 * (DINq * Hq / 4);
    const float4* w2 = (const float4*)W_exp + (size_t)e2 * (DINq * Hq / 4);
    float4 a = w1[idx], c = w2[idx];
    float4 r = make_float4(g1 * a.x + g2 * c.x, g1 * a.y + g2 * c.y,
                           g1 * a.z + g2 * c.z, g1 * a.w + g2 * c.w);
    ((float4*)g_Wcomb)[(size_t)b * (DINq * Hq / 4) + idx] = r;
}

// ---------------- K3: fused GEMM  [Y | SH] = dte @ [Wcomb_b | W_sh] ----------------
// tile 128x128, BK=16, 256 threads, per-thread 8x8 via f32x2, double-buffered.
__global__ void __launch_bounds__(256) k_gemmA(
    const float* __restrict__ dte,
    const float* __restrict__ W_sh, const float* __restrict__ b_sh) {
    __shared__ float As[2][16][128];
    __shared__ float Bs[2][16][128];
    int b = blockIdx.y, mx = blockIdx.x;
    const float* A  = dte + ((size_t)b * Lq + mx * 128) * DINq;
    const float* Wc = g_Wcomb + (size_t)b * DINq * Hq;
    int tid = threadIdx.x;
    int tx = tid & 15, ty = tid >> 4;

    ull acc[8][4];
#pragma unroll
    for (int i = 0; i < 8; i++)
#pragma unroll
        for (int j = 0; j < 4; j++) acc[i][j] = 0ull;

    // prologue load into buf 0
#pragma unroll
    for (int i = 0; i < 2; i++) {
        int idx = i * 256 + tid;
        int r = idx >> 2, c4 = idx & 3;
        float4 v = *(const float4*)(A + (size_t)r * DINq + c4 * 4);
        As[0][c4 * 4 + 0][r] = v.x;
        As[0][c4 * 4 + 1][r] = v.y;
        As[0][c4 * 4 + 2][r] = v.z;
        As[0][c4 * 4 + 3][r] = v.w;
        int kq = idx >> 5, n4 = idx & 31;
        float4 w = (n4 < 16)
            ? *(const float4*)(Wc + (size_t)kq * Hq + n4 * 4)
            : *(const float4*)(W_sh + (size_t)kq * Hq + (n4 - 16) * 4);
        *(float4*)&Bs[0][kq][n4 * 4] = w;
    }
    __syncthreads();

    for (int k0 = 0; k0 < DINq; k0 += 16) {
        int buf = (k0 >> 4) & 1;
        if (k0 + 16 < DINq) {
            int kn = k0 + 16;
#pragma unroll
            for (int i = 0; i < 2; i++) {
                int idx = i * 256 + tid;
                int r = idx >> 2, c4 = idx & 3;
                float4 v = *(const float4*)(A + (size_t)r * DINq + kn + c4 * 4);
                As[buf ^ 1][c4 * 4 + 0][r] = v.x;
                As[buf ^ 1][c4 * 4 + 1][r] = v.y;
                As[buf ^ 1][c4 * 4 + 2][r] = v.z;
                As[buf ^ 1][c4 * 4 + 3][r] = v.w;
                int kq = idx >> 5, n4 = idx & 31;
                float4 w = (n4 < 16)
                    ? *(const float4*)(Wc + (size_t)(kn + kq) * Hq + n4 * 4)
                    : *(const float4*)(W_sh + (size_t)(kn + kq) * Hq + (n4 - 16) * 4);
                *(float4*)&Bs[buf ^ 1][kq][n4 * 4] = w;
            }
        }
#pragma unroll
        for (int kk = 0; kk < 16; kk++) {
            float4 a0 = *(const float4*)&As[buf][kk][ty * 8];
            float4 a1 = *(const float4*)&As[buf][kk][ty * 8 + 4];
            ulonglong2 b0 = *(const ulonglong2*)&Bs[buf][kk][tx * 8];
            ulonglong2 b1 = *(const ulonglong2*)&Bs[buf][kk][tx * 8 + 4];
            ull bb[4] = {b0.x, b0.y, b1.x, b1.y};
            ull ap[8];
            ap[0] = pk2(a0.x); ap[1] = pk2(a0.y); ap[2] = pk2(a0.z); ap[3] = pk2(a0.w);
            ap[4] = pk2(a1.x); ap[5] = pk2(a1.y); ap[6] = pk2(a1.z); ap[7] = pk2(a1.w);
#pragma unroll
            for (int i = 0; i < 8; i++)
#pragma unroll
                for (int j = 0; j < 4; j++)
                    acc[i][j] = fma2(ap[i], bb[j], acc[i][j]);
        }
        __syncthreads();
    }

    // epilogue: cols tx*8..tx*8+7 ; tx<8 -> Y, else -> SH
    float bcol[8];
    float* C;
    int cc;
    if (tx < 8) {
        C = g_Y; cc = tx * 8;
#pragma unroll
        for (int j = 0; j < 8; j++) bcol[j] = g_gbias[b * Hq + cc + j];
    } else {
        C = g_SH; cc = (tx - 8) * 8;
#pragma unroll
        for (int j = 0; j < 8; j++) bcol[j] = b_sh[cc + j];
    }
    size_t rowbase = ((size_t)b * Lq + mx * 128 + ty * 8);
#pragma unroll
    for (int i = 0; i < 8; i++) {
        float o[8];
#pragma unroll
        for (int j = 0; j < 4; j++) {
            float2 f = unpk(acc[i][j]);
            o[2 * j] = f.x + bcol[2 * j];
            o[2 * j + 1] = f.y + bcol[2 * j + 1];
        }
        float* cp = C + (rowbase + i) * Hq + cc;
        *(float4*)cp = make_float4(o[0], o[1], o[2], o[3]);
        *(float4*)(cp + 4) = make_float4(o[4], o[5], o[6], o[7]);
    }
}

// ---------------- K3b: RGB GEMM, tile 128x64, per-thread 8x4 ----------------
__global__ void __launch_bounds__(256) k_gemmB(
    const float* __restrict__ x,
    const float* __restrict__ W_rgb, const float* __restrict__ b_rgb) {
    __shared__ float As[2][16][128];
    __shared__ float Bs[2][16][64];
    const float* A = x + (size_t)blockIdx.x * 128 * DINq;
    int tid = threadIdx.x;
    int tx = tid & 15, ty = tid >> 4;

    ull acc[8][2];
#pragma unroll
    for (int i = 0; i < 8; i++) { acc[i][0] = 0ull; acc[i][1] = 0ull; }

#pragma unroll
    for (int i = 0; i < 2; i++) {
        int idx = i * 256 + tid;
        int r = idx >> 2, c4 = idx & 3;
        float4 v = *(const float4*)(A + (size_t)r * DINq + c4 * 4);
        As[0][c4 * 4 + 0][r] = v.x;
        As[0][c4 * 4 + 1][r] = v.y;
        As[0][c4 * 4 + 2][r] = v.z;
        As[0][c4 * 4 + 3][r] = v.w;
    }
    {
        int kq = tid >> 4, n4 = tid & 15;
        *(float4*)&Bs[0][kq][n4 * 4] =
            *(const float4*)(W_rgb + (size_t)kq * Hq + n4 * 4);
    }
    __syncthreads();

    for (int k0 = 0; k0 < DINq; k0 += 16) {
        int buf = (k0 >> 4) & 1;
        if (k0 + 16 < DINq) {
            int kn = k0 + 16;
#pragma unroll
            for (int i = 0; i < 2; i++) {
                int idx = i * 256 + tid;
                int r = idx >> 2, c4 = idx & 3;
                float4 v = *(const float4*)(A + (size_t)r * DINq + kn + c4 * 4);
                As[buf ^ 1][c4 * 4 + 0][r] = v.x;
                As[buf ^ 1][c4 * 4 + 1][r] = v.y;
                As[buf ^ 1][c4 * 4 + 2][r] = v.z;
                As[buf ^ 1][c4 * 4 + 3][r] = v.w;
            }
            int kq = tid >> 4, n4 = tid & 15;
            *(float4*)&Bs[buf ^ 1][kq][n4 * 4] =
                *(const float4*)(W_rgb + (size_t)(kn + kq) * Hq + n4 * 4);
        }
#pragma unroll
        for (int kk = 0; kk < 16; kk++) {
            float4 a0 = *(const float4*)&As[buf][kk][ty * 8];
            float4 a1 = *(const float4*)&As[buf][kk][ty * 8 + 4];
            ulonglong2 bv = *(const ulonglong2*)&Bs[buf][kk][tx * 4];
            ull ap[8];
            ap[0] = pk2(a0.x); ap[1] = pk2(a0.y); ap[2] = pk2(a0.z); ap[3] = pk2(a0.w);
            ap[4] = pk2(a1.x); ap[5] = pk2(a1.y); ap[6] = pk2(a1.z); ap[7] = pk2(a1.w);
#pragma unroll
            for (int i = 0; i < 8; i++) {
                acc[i][0] = fma2(ap[i], bv.x, acc[i][0]);
                acc[i][1] = fma2(ap[i], bv.y, acc[i][1]);
            }
        }
        __syncthreads();
    }

    float bcol[4];
#pragma unroll
    for (int j = 0; j < 4; j++) bcol[j] = b_rgb[tx * 4 + j];
    size_t rowbase = (size_t)blockIdx.x * 128 + ty * 8;
#pragma unroll
    for (int i = 0; i < 8; i++) {
        float2 f0 = unpk(acc[i][0]);
        float2 f1 = unpk(acc[i][1]);
        *(float4*)(g_RGB + (rowbase + i) * Hq + tx * 4) =
            make_float4(f0.x + bcol[0], f0.y + bcol[1],
                        f1.x + bcol[2], f1.y + bcol[3]);
    }
}

// ---------------- K4: LayerNorm + W_px (4 threads / token) ----------------
__global__ void __launch_bounds__(256) k_preln(
    const float* __restrict__ W_px, const float* __restrict__ b_px,
    const float* __restrict__ ln_g, const float* __restrict__ ln_b) {
    extern __shared__ float sm[];
    float* s_w = sm;            // 64 x 128
    float* s_t = sm + 8192;     // 64 tokens x 68

    int tid = threadIdx.x;
    for (int i = tid; i < 2048; i += 256)
        ((float4*)s_w)[i] = ((const float4*)W_px)[i];

    int tok = tid >> 2, q = tid & 3;
    int t = blockIdx.x * 64 + tok;
    const float* shp = g_SH + (size_t)t * Hq + q * 16;
    float v[16];
#pragma unroll
    for (int c = 0; c < 4; c++)
        *(float4*)(v + c * 4) = *(const float4*)(shp + c * 4);
    float s = 0.0f, s2 = 0.0f;
#pragma unroll
    for (int u = 0; u < 16; u++) { s += v[u]; s2 += v[u] * v[u]; }
    s  += __shfl_xor_sync(0xffffffffu, s, 1);
    s  += __shfl_xor_sync(0xffffffffu, s, 2);
    s2 += __shfl_xor_sync(0xffffffffu, s2, 1);
    s2 += __shfl_xor_sync(0xffffffffu, s2, 2);
    float mean = s * (1.0f / Hq);
    float var = s2 * (1.0f / Hq) - mean * mean;
    float rstd = rsqrtf(var + 1e-6f);

    float* tr = s_t + tok * 68;
#pragma unroll
    for (int u = 0; u < 16; u++)
        tr[q * 16 + u] = (v[u] - mean) * rstd * __ldg(ln_g + q * 16 + u)
                       + __ldg(ln_b + q * 16 + u);
    __syncthreads();   // covers s_w load and s_t writes

    // matmul: cols q*32 .. q*32+31
    ull acc[16];
    {
        const ulonglong2* bp = (const ulonglong2*)(b_px + q * 32);
#pragma unroll
        for (int j = 0; j < 8; j++) {
            ulonglong2 bv = __ldg(bp + j);
            acc[2 * j] = bv.x; acc[2 * j + 1] = bv.y;
        }
    }
#pragma unroll 4
    for (int h = 0; h < 64; h++) {
        ull in2 = pk2(tr[h]);
        const ulonglong2* wr = (const ulonglong2*)(s_w + h * 128 + q * 32);
#pragma unroll
        for (int j = 0; j < 8; j++) {
            ulonglong2 wv = wr[j];
            acc[2 * j] = fma2(in2, wv.x, acc[2 * j]);
            acc[2 * j + 1] = fma2(in2, wv.y, acc[2 * j + 1]);
        }
    }
    float* outp = g_T + (size_t)t * 128 + q * 32;
#pragma unroll
    for (int j = 0; j < 8; j++) {
        float2 f0 = unpk(acc[2 * j]);
        float2 f1 = unpk(acc[2 * j + 1]);
        *(float4*)(outp + j * 4) = make_float4(f0.x, f0.y, f1.x, f1.y);
    }
}

// ---------------- matvec helper: 16 outputs (cols q*16..) via f32x2 ----------------
__device__ __forceinline__ void mm16(const float* __restrict__ in,
                                     const float* __restrict__ w,
                                     int q, ull acc[8]) {
#pragma unroll 8
    for (int h = 0; h < 64; h++) {
        ull in2 = pk2(in[h]);
        const ulonglong2* wr = (const ulonglong2*)(w + h * 64 + q * 16);
#pragma unroll
        for (int j = 0; j < 4; j++) {
            ulonglong2 wv = wr[j];
            acc[2 * j] = fma2(in2, wv.x, acc[2 * j]);
            acc[2 * j + 1] = fma2(in2, wv.y, acc[2 * j + 1]);
        }
    }
}
__device__ __forceinline__ void bias_init(const float* __restrict__ bias,
                                          int q, ull acc[8]) {
    const ulonglong2* bp = (const ulonglong2*)(bias + q * 16);
#pragma unroll
    for (int j = 0; j < 4; j++) {
        ulonglong2 bv = __ldg(bp + j);
        acc[2 * j] = bv.x; acc[2 * j + 1] = bv.y;
    }
}
__device__ __forceinline__ void unpack16(const ull acc[8], float o[16]) {
#pragma unroll
    for (int j = 0; j < 8; j++) {
        float2 f = unpk(acc[j]);
        o[2 * j] = f.x; o[2 * j + 1] = f.y;
    }
}

// ---------------- K5: conv + GLU + matmul chain (4 threads / token) ----------------
__global__ void __launch_bounds__(256) k_post(
    const float* __restrict__ conv_sh,
    const float* __restrict__ W_pxx,    const float* __restrict__ b_pxx,
    const float* __restrict__ W_dte,    const float* __restrict__ b_dte,
    const float* __restrict__ W_dteall, const float* __restrict__ b_dteall,
    const float* __restrict__ W_fmod,   const float* __restrict__ b_fmod,
    const float* __restrict__ W_fx,     const float* __restrict__ b_fx,
    const float* __restrict__ W_fxx,    const float* __restrict__ b_fxx,
    float* __restrict__ d_out) {
    extern __shared__ float sm[];
    float* s_pxx    = sm;
    float* s_dte    = sm + 4096;
    float* s_dteall = sm + 8192;
    float* s_fmod   = sm + 12288;
    float* s_fx     = sm + 16384;
    float* s_fxx    = sm + 20480;
    float* s_cv     = sm + 24576;            // [tap][h] 576
    float* sA       = sm + 25152;            // 64 x 68
    float* sB       = sA + 4352;
    float* sC       = sB + 4352;

    int tid = threadIdx.x;
    {
        const float* wsrc[6] = {W_pxx, W_dte, W_dteall, W_fmod, W_fx, W_fxx};
#pragma unroll
        for (int m = 0; m < 6; m++)
            for (int i = tid; i < 1024; i += 256)
                ((float4*)(sm + m * 4096))[i] = ((const float4*)wsrc[m])[i];
        for (int i = tid; i < 576; i += 256) {
            int tap = i >> 6, h = i & 63;
            s_cv[i] = conv_sh[h * 9 + tap];
        }
    }
    __syncthreads();

    int tok = tid >> 2, q = tid & 3;
    int t = blockIdx.x * 64 + tok;
    int l = t & 255, ii = l >> 4, jj = l & 15;
    float* rA = sA + tok * 68;
    float* rB = sB + tok * 68;
    float* rC = sC + tok * 68;

    // preload Y row segment -> rC
#pragma unroll
    for (int c = 0; c < 4; c++)
        *(float4*)(rC + q * 16 + c * 4) =
            *(const float4*)(g_Y + (size_t)t * 64 + q * 16 + c * 4);

    // stage 1: rA = gelu(conv(t1)) * t2
#pragma unroll
    for (int c = 0; c < 4; c++) {
        int h0 = q * 16 + c * 4;
        float4 acc = make_float4(0.f, 0.f, 0.f, 0.f);
#pragma unroll
        for (int tap = 0; tap < 9; tap++) {
            int di = tap / 3 - 1, dj = tap % 3 - 1;
            int ni = ii + di, nj = jj + dj;
            if (ni < 0 || ni > 15 || nj < 0 || nj > 15) continue;
            float4 v = *(const float4*)(g_T + (size_t)(t + di * 16 + dj) * 128 + h0);
            float4 w = *(const float4*)(s_cv + tap * 64 + h0);
            acc = f4add(acc, f4mul(v, w));
        }
        float4 t2 = *(const float4*)(g_T + (size_t)t * 128 + 64 + h0);
        *(float4*)(rA + h0) = f4mul(gelu4(acc), t2);
    }
    __syncwarp();

    // stage 2: rB = rA @ W_pxx + b_pxx + SH
    {
        ull acc[8]; bias_init(b_pxx, q, acc);
        mm16(rA, s_pxx, q, acc);
        float o[16]; unpack16(acc, o);
#pragma unroll
        for (int c = 0; c < 4; c++) {
            float4 shv = *(const float4*)(g_SH + (size_t)t * 64 + q * 16 + c * 4);
            float4 ov = *(float4*)(o + c * 4);
            *(float4*)(rB + q * 16 + c * 4) = f4add(ov, shv);
        }
    }
    __syncwarp();

    // stage 3: rA = gelu(rC@W_dte + rB@W_dteall + b_dte + b_dteall)
    {
        ull acc[8]; bias_init(b_dte, q, acc);
        mm16(rC, s_dte, q, acc);
        mm16(rB, s_dteall, q, acc);
        float o[16]; unpack16(acc, o);
#pragma unroll
        for (int u = 0; u < 16; u++)
            o[u] = gelu1(o[u] + __ldg(b_dteall + q * 16 + u));
#pragma unroll
        for (int c = 0; c < 4; c++)
            *(float4*)(rA + q * 16 + c * 4) = *(float4*)(o + c * 4);
    }
    __syncwarp();

    // stage 4: rB = gelu(rA @ W_fmod + b_fmod) ; rC = gelu(rgb)
    float rgbv[16];
    {
        ull acc[8]; bias_init(b_fmod, q, acc);
        mm16(rA, s_fmod, q, acc);
        float o[16]; unpack16(acc, o);
#pragma unroll
        for (int u = 0; u < 16; u++) o[u] = gelu1(o[u]);
#pragma unroll
        for (int c = 0; c < 4; c++)
            *(float4*)(rB + q * 16 + c * 4) = *(float4*)(o + c * 4);
#pragma unroll
        for (int c = 0; c < 4; c++)
            *(float4*)(rgbv + c * 4) =
                *(const float4*)(g_RGB + (size_t)t * 64 + q * 16 + c * 4);
#pragma unroll
        for (int u = 0; u < 16; u++) rC[q * 16 + u] = gelu1(rgbv[u]);
    }
    __syncwarp();

    // stage 5: a = rC @ W_fx + b_fx ; rA = rB(own) * a
    {
        ull acc[8]; bias_init(b_fx, q, acc);
        mm16(rC, s_fx, q, acc);
        float o[16]; unpack16(acc, o);
#pragma unroll
        for (int u = 0; u < 16; u++) o[u] *= rB[q * 16 + u];
#pragma unroll
        for (int c = 0; c < 4; c++)
            *(float4*)(rA + q * 16 + c * 4) = *(float4*)(o + c * 4);
    }
    __syncwarp();

    // stage 6: out = rA @ W_fxx + b_fxx + rgb
    {
        ull acc[8]; bias_init(b_fxx, q, acc);
        mm16(rA, s_fxx, q, acc);
        float o[16]; unpack16(acc, o);
#pragma unroll
        for (int c = 0; c < 4; c++) {
            float4 ov = *(float4*)(o + c * 4);
            float4 rv = *(float4*)(rgbv + c * 4);
            *(float4*)(d_out + (size_t)t * 64 + q * 16 + c * 4) = f4add(ov, rv);
        }
    }
}

// ---------------- host launcher ----------------
extern "C" void kernel_launch(void* const* d_in, const int* in_sizes, int n_in,
                              void* d_out, int out_size) {
    const float* x        = (const float*)d_in[0];
    const float* dte      = (const float*)d_in[1];
    const float* w_gate   = (const float*)d_in[2];
    const float* W_exp    = (const float*)d_in[3];
    const float* b_exp    = (const float*)d_in[4];
    const float* W_sh     = (const float*)d_in[5];
    const float* b_sh     = (const float*)d_in[6];
    const float* ln_g     = (const float*)d_in[7];
    const float* ln_b     = (const float*)d_in[8];
    const float* W_px     = (const float*)d_in[9];
    const float* b_px     = (const float*)d_in[10];
    const float* conv_sh  = (const float*)d_in[11];
    const float* W_pxx    = (const float*)d_in[12];
    const float* b_pxx    = (const float*)d_in[13];
    const float* W_dte    = (const float*)d_in[14];
    const float* b_dte    = (const float*)d_in[15];
    const float* W_dteall = (const float*)d_in[16];
    const float* b_dteall = (const float*)d_in[17];
    const float* W_rgb    = (const float*)d_in[18];
    const float* b_rgb    = (const float*)d_in[19];
    const float* W_fx     = (const float*)d_in[20];
    const float* b_fx     = (const float*)d_in[21];
    const float* W_fmod   = (const float*)d_in[22];
    const float* b_fmod   = (const float*)d_in[23];
    const float* W_fxx    = (const float*)d_in[24];
    const float* b_fxx    = (const float*)d_in[25];
    float* out = (float*)d_out;

    cudaFuncSetAttribute(k_preln, cudaFuncAttributeMaxDynamicSharedMemorySize, 50176);
    cudaFuncSetAttribute(k_post,  cudaFuncAttributeMaxDynamicSharedMemorySize, 152832);

    k_mean<<<NT / 8, 256>>>(dte);
    k_gate<<<1, 64>>>(w_gate, b_exp, out, out_size - 1);
    k_wcomb<<<dim3(48, Bq), 256>>>(W_exp);

    k_gemmA<<<dim3(2, Bq), 256>>>(dte, W_sh, b_sh);
    k_gemmB<<<128, 256>>>(x, W_rgb, b_rgb);

    k_preln<<<256, 256, 50176>>>(W_px, b_px, ln_g, ln_b);
    k_post<<<256, 256, 152832>>>(conv_sh,
                                 W_pxx, b_pxx, W_dte, b_dte, W_dteall, b_dteall,
                                 W_fmod, b_fmod, W_fx, b_fx, W_fxx, b_fxx,
                                 out);
}

// round 4
// speedup vs baseline: 1.2556x; 1.2556x over previous
#include <cuda_runtime.h>
#include <cuda_bf16.h>
#include <math.h>
#include <stdint.h>

#define Bq   64
#define Lq   256
#define DINq 768
#define Hq   64
#define Eq   8
#define NT   (Bq * Lq)

// ---------------- device scratch ----------------
__device__ float g_mean[NT];
__device__ int   g_e1[Bq], g_e2[Bq];
__device__ float g_g1[Bq], g_g2[Bq];
__device__ float g_gbias[Bq * Hq];
__device__ float g_Y  [NT * Hq];
__device__ float g_SH [NT * Hq];
__device__ float g_RGB[NT * Hq];
__device__ float g_T  [NT * 2 * Hq];

// ---------------- helpers ----------------
__device__ __forceinline__ float gelu1(float x) {
    return 0.5f * x * (1.0f + erff(x * 0.7071067811865475f));
}
__device__ __forceinline__ float4 f4add(float4 a, float4 b) {
    return make_float4(a.x + b.x, a.y + b.y, a.z + b.z, a.w + b.w);
}
__device__ __forceinline__ float4 f4mul(float4 a, float4 b) {
    return make_float4(a.x * b.x, a.y * b.y, a.z * b.z, a.w * b.w);
}
__device__ __forceinline__ float4 gelu4(float4 a) {
    return make_float4(gelu1(a.x), gelu1(a.y), gelu1(a.z), gelu1(a.w));
}
__device__ __forceinline__ uint32_t smem_u32(const void* p) {
    uint32_t a;
    asm("{ .reg .u64 t; cvta.to.shared.u64 t, %1; cvt.u32.u64 %0, t; }"
        : "=r"(a) : "l"(p));
    return a;
}
__device__ __forceinline__ uint32_t swz(uint32_t off) {
    return off ^ ((off >> 3) & 0x70u);
}
__device__ __forceinline__ uint32_t pack_split(float f0, float f1, uint32_t& lo) {
    __nv_bfloat16 h0 = __float2bfloat16(f0);
    __nv_bfloat16 h1 = __float2bfloat16(f1);
    __nv_bfloat16 l0 = __float2bfloat16(f0 - __bfloat162float(h0));
    __nv_bfloat16 l1 = __float2bfloat16(f1 - __bfloat162float(h1));
    lo = ((uint32_t)__bfloat16_as_ushort(l1) << 16) | (uint32_t)__bfloat16_as_ushort(l0);
    return ((uint32_t)__bfloat16_as_ushort(h1) << 16) | (uint32_t)__bfloat16_as_ushort(h0);
}
__device__ __forceinline__ void ldsm_x4(uint32_t addr, uint32_t r[4]) {
    asm volatile("ldmatrix.sync.aligned.m8n8.x4.shared.b16 {%0,%1,%2,%3}, [%4];"
                 : "=r"(r[0]), "=r"(r[1]), "=r"(r[2]), "=r"(r[3]) : "r"(addr));
}
__device__ __forceinline__ void mma_bf16(float c[4], const uint32_t a[4],
                                         uint32_t b0, uint32_t b1) {
    asm volatile(
        "mma.sync.aligned.m16n8k16.row.col.f32.bf16.bf16.f32 "
        "{%0,%1,%2,%3}, {%4,%5,%6,%7}, {%8,%9}, {%0,%1,%2,%3};"
        : "+f"(c[0]), "+f"(c[1]), "+f"(c[2]), "+f"(c[3])
        : "r"(a[0]), "r"(a[1]), "r"(a[2]), "r"(a[3]), "r"(b0), "r"(b1));
}

// ---------------- K0: row mean ----------------
__global__ void k_mean(const float* __restrict__ dte) {
    int w = threadIdx.x >> 5, lane = threadIdx.x & 31;
    int row = blockIdx.x * 8 + w;
    const float* p = dte + (size_t)row * DINq + lane;
    float s = 0.0f;
#pragma unroll
    for (int k = 0; k < DINq / 32; k++) s += p[k * 32];
#pragma unroll
    for (int o = 16; o; o >>= 1) s += __shfl_xor_sync(0xffffffffu, s, o);
    if (lane == 0) g_mean[row] = s * (1.0f / (float)DINq);
}

// ---------------- K1: gating ----------------
__global__ void k_gate(const float* __restrict__ w_gate,
                       const float* __restrict__ b_exp,
                       float* __restrict__ d_out, int loss_idx) {
    __shared__ float s_imp[Eq];
    __shared__ float s_load[Eq];
    int b = threadIdx.x;
    if (b < Eq) { s_imp[b] = 0.0f; s_load[b] = 0.0f; }
    __syncthreads();

    float lg[Eq];
#pragma unroll
    for (int e = 0; e < Eq; e++) lg[e] = 0.0f;
    for (int l = 0; l < Lq; l++) {
        float m = g_mean[b * Lq + l];
#pragma unroll
        for (int e = 0; e < Eq; e++) lg[e] += m * w_gate[l * Eq + e];
    }
    int e1 = 0;
    for (int e = 1; e < Eq; e++) if (lg[e] > lg[e1]) e1 = e;
    int e2 = -1;
    for (int e = 0; e < Eq; e++) {
        if (e == e1) continue;
        if (e2 < 0 || lg[e] > lg[e2]) e2 = e;
    }
    float v1 = lg[e1], v2 = lg[e2];
    float ex = expf(v2 - v1);
    float den = 1.0f / (1.0f + ex);
    float g1 = den, g2 = ex * den;

    g_e1[b] = e1; g_e2[b] = e2; g_g1[b] = g1; g_g2[b] = g2;
    for (int h = 0; h < Hq; h++)
        g_gbias[b * Hq + h] = g1 * b_exp[e1 * Hq + h] + g2 * b_exp[e2 * Hq + h];

    atomicAdd(&s_imp[e1], g1);
    atomicAdd(&s_imp[e2], g2);
    atomicAdd(&s_load[e1], 1.0f);
    atomicAdd(&s_load[e2], 1.0f);
    __syncthreads();

    if (b == 0) {
        float m1 = 0.0f, m2 = 0.0f;
        for (int e = 0; e < Eq; e++) { m1 += s_imp[e]; m2 += s_load[e]; }
        m1 *= (1.0f / Eq); m2 *= (1.0f / Eq);
        float var1 = 0.0f, var2 = 0.0f;
        for (int e = 0; e < Eq; e++) {
            float d1 = s_imp[e] - m1;  var1 += d1 * d1;
            float d2 = s_load[e] - m2; var2 += d2 * d2;
        }
        var1 *= (1.0f / (Eq - 1)); var2 *= (1.0f / (Eq - 1));
        d_out[loss_idx] = 0.01f * (var1 / (m1 * m1 + 1e-10f) +
                                   var2 / (m2 * m2 + 1e-10f));
    }
}

// ---------------- K3: mma.sync bf16x3 GEMM ----------------
// blocks 0..127  : job A — C[128,128] = dte_tile @ [g1*We1+g2*We2 | W_sh] -> Y|SH
// blocks 128..255: job B — C[128,64]  = x_tile @ W_rgb                   -> RGB
// smem (65536 B): A_hi 16K | A_lo 16K | BT_hi 16K | BT_lo 16K
#define OFF_AHI 0u
#define OFF_ALO 16384u
#define OFF_BHI 32768u
#define OFF_BLO 49152u
#define SMEM_MM 65536

__global__ void __launch_bounds__(256, 1) k_gemm_mma(
    const float* __restrict__ dte, const float* __restrict__ x,
    const float* __restrict__ W_exp,
    const float* __restrict__ W_sh, const float* __restrict__ b_sh,
    const float* __restrict__ W_rgb, const float* __restrict__ b_rgb) {
    extern __shared__ char smc[];
    uint32_t sb = smem_u32(smc);
    int tid = threadIdx.x, lane = tid & 31, wid = tid >> 5;
    int bidx = blockIdx.x;
    bool jobA = bidx < 128;

    const float* Asrc;
    const float* We1 = nullptr;
    const float* We2 = nullptr;
    float gg1 = 0.f, gg2 = 0.f;
    int bb = 0, mx = 0, mt_ = 0;
    if (jobA) {
        bb = bidx >> 1; mx = bidx & 1;
        Asrc = dte + ((size_t)bb * Lq + mx * 128) * DINq;
        We1 = W_exp + (size_t)g_e1[bb] * DINq * Hq;
        We2 = W_exp + (size_t)g_e2[bb] * DINq * Hq;
        gg1 = g_g1[bb]; gg2 = g_g2[bb];
    } else {
        mt_ = bidx - 128;
        Asrc = x + (size_t)mt_ * 128 * DINq;
    }

    int wm = wid & 3, wn = wid >> 2;
    int nTiles = jobA ? 8 : 4;           // per warp (n8 tiles)
    int m_base = wm * 32;
    int n_base = wn * (jobA ? 64 : 32);

    float c[2][8][4];
#pragma unroll
    for (int mt = 0; mt < 2; mt++)
#pragma unroll
        for (int nt = 0; nt < 8; nt++)
#pragma unroll
            for (int j = 0; j < 4; j++) c[mt][nt][j] = 0.0f;

    // ldmatrix lane address components (A tiles, m16 x k16)
    int lr = lane & 7, sel = lane >> 3;
    int a_row_off = ((sel & 1) << 3) + lr;     // +8 rows for odd sel
    int a_kb_off  = (sel >> 1) << 4;           // +16 bytes for k+8

    for (int ch = 0; ch < 12; ch++) {
        int k0 = ch * 64;

        // ---- convert A tile 128x64 fp32 -> bf16 hi/lo, swizzled K-major ----
#pragma unroll
        for (int i = 0; i < 2; i++) {
            int task = tid + i * 256;          // (row, kseg of 16)
            int row = task >> 2, kseg = task & 3;
            const float* src = Asrc + (size_t)row * DINq + k0 + kseg * 16;
            uint32_t hu[8], lu[8];
#pragma unroll
            for (int j = 0; j < 4; j++) {
                float4 v = *(const float4*)(src + j * 4);
                hu[j * 2]     = pack_split(v.x, v.y, lu[j * 2]);
                hu[j * 2 + 1] = pack_split(v.z, v.w, lu[j * 2 + 1]);
            }
            uint32_t base = (uint32_t)row * 128u + (uint32_t)kseg * 32u;
            uint32_t o0 = swz(base), o1 = swz(base + 16u);
            *(uint4*)(smc + OFF_AHI + o0) = make_uint4(hu[0], hu[1], hu[2], hu[3]);
            *(uint4*)(smc + OFF_AHI + o1) = make_uint4(hu[4], hu[5], hu[6], hu[7]);
            *(uint4*)(smc + OFF_ALO + o0) = make_uint4(lu[0], lu[1], lu[2], lu[3]);
            *(uint4*)(smc + OFF_ALO + o1) = make_uint4(lu[4], lu[5], lu[6], lu[7]);
        }

        // ---- convert B tile -> BT[n][k] bf16 hi/lo (transposed, swizzled) ----
        if (jobA) {
#pragma unroll
            for (int i = 0; i < 8; i++) {
                int task = tid + i * 256;      // 2048: k(64) x nq(32)
                int k = task >> 5, nq = task & 31;
                float4 v;
                if (nq < 16) {
                    float4 v1 = *(const float4*)(We1 + (size_t)(k0 + k) * Hq + nq * 4);
                    float4 v2 = *(const float4*)(We2 + (size_t)(k0 + k) * Hq + nq * 4);
                    v = make_float4(gg1 * v1.x + gg2 * v2.x, gg1 * v1.y + gg2 * v2.y,
                                    gg1 * v1.z + gg2 * v2.z, gg1 * v1.w + gg2 * v2.w);
                } else {
                    v = *(const float4*)(W_sh + (size_t)(k0 + k) * Hq + (nq - 16) * 4);
                }
                float f[4] = {v.x, v.y, v.z, v.w};
#pragma unroll
                for (int j = 0; j < 4; j++) {
                    int n = nq * 4 + j;
                    __nv_bfloat16 h = __float2bfloat16(f[j]);
                    __nv_bfloat16 l = __float2bfloat16(f[j] - __bfloat162float(h));
                    uint32_t off = swz((uint32_t)n * 128u + (uint32_t)k * 2u);
                    *(__nv_bfloat16*)(smc + OFF_BHI + off) = h;
                    *(__nv_bfloat16*)(smc + OFF_BLO + off) = l;
                }
            }
        } else {
#pragma unroll
            for (int i = 0; i < 4; i++) {
                int task = tid + i * 256;      // 1024: k(64) x nq(16)
                int k = task >> 4, nq = task & 15;
                float4 v = *(const float4*)(W_rgb + (size_t)(k0 + k) * Hq + nq * 4);
                float f[4] = {v.x, v.y, v.z, v.w};
#pragma unroll
                for (int j = 0; j < 4; j++) {
                    int n = nq * 4 + j;
                    __nv_bfloat16 h = __float2bfloat16(f[j]);
                    __nv_bfloat16 l = __float2bfloat16(f[j] - __bfloat162float(h));
                    uint32_t off = swz((uint32_t)n * 128u + (uint32_t)k * 2u);
                    *(__nv_bfloat16*)(smc + OFF_BHI + off) = h;
                    *(__nv_bfloat16*)(smc + OFF_BLO + off) = l;
                }
            }
        }
        __syncthreads();

        // ---- compute: 4 ksteps of 16 ----
#pragma unroll
        for (int ks = 0; ks < 4; ks++) {
            int kbyte = ks * 32;
            uint32_t ahi[2][4], alo[2][4];
#pragma unroll
            for (int mt = 0; mt < 2; mt++) {
                uint32_t ro = (uint32_t)((m_base + mt * 16 + a_row_off) * 128
                                         + kbyte + a_kb_off);
                uint32_t so = swz(ro);
                ldsm_x4(sb + OFF_AHI + so, ahi[mt]);
                ldsm_x4(sb + OFF_ALO + so, alo[mt]);
            }
            int nb = n_base + (lane >> 2);
            int kk = ks * 16 + (lane & 3) * 2;
            for (int nt = 0; nt < nTiles; nt++) {
                uint32_t off0 = swz((uint32_t)((nb + nt * 8) * 128 + kk * 2));
                uint32_t off1 = swz((uint32_t)((nb + nt * 8) * 128 + (kk + 8) * 2));
                uint32_t bh0 = *(const uint32_t*)(smc + OFF_BHI + off0);
                uint32_t bh1 = *(const uint32_t*)(smc + OFF_BHI + off1);
                uint32_t bl0 = *(const uint32_t*)(smc + OFF_BLO + off0);
                uint32_t bl1 = *(const uint32_t*)(smc + OFF_BLO + off1);
#pragma unroll
                for (int mt = 0; mt < 2; mt++) {
                    mma_bf16(c[mt][nt], ahi[mt], bh0, bh1);
                    mma_bf16(c[mt][nt], ahi[mt], bl0, bl1);
                    mma_bf16(c[mt][nt], alo[mt], bh0, bh1);
                }
            }
        }
        __syncthreads();
    }

    // ---- epilogue: frags + bias -> gmem ----
    int rg = lane >> 2, tg = lane & 3;
    for (int mt = 0; mt < 2; mt++) {
        for (int nt = 0; nt < nTiles; nt++) {
            int col = n_base + nt * 8 + tg * 2;
            int row0 = m_base + mt * 16 + rg;
            float* dst;
            const float* bias;
            int cc;
            size_t t0;
            if (!jobA) {
                dst = g_RGB; bias = b_rgb; cc = col;
                t0 = (size_t)mt_ * 128;
            } else if (col < 64) {
                dst = g_Y; bias = g_gbias + bb * 64; cc = col;
                t0 = (size_t)bb * Lq + mx * 128;
            } else {
                dst = g_SH; bias = b_sh; cc = col - 64;
                t0 = (size_t)bb * Lq + mx * 128;
            }
            float b0 = bias[cc], b1 = bias[cc + 1];
            float* p0 = dst + (t0 + row0) * Hq + cc;
            float* p1 = dst + (t0 + row0 + 8) * Hq + cc;
            p0[0] = c[mt][nt][0] + b0;  p0[1] = c[mt][nt][1] + b1;
            p1[0] = c[mt][nt][2] + b0;  p1[1] = c[mt][nt][3] + b1;
        }
    }
}

// ---------------- K4: LayerNorm + W_px -> T (t1|t2)  [R1 version] ----------------
__global__ void __launch_bounds__(128) k_preln(
    const float* __restrict__ W_px, const float* __restrict__ b_px,
    const float* __restrict__ ln_g, const float* __restrict__ ln_b) {
    extern __shared__ float sm[];
    float* s_w = sm;             // 8192
    float* s_g = sm + 8192;      // 64
    float* s_b = sm + 8256;      // 64
    float* s_t = sm + 8320;      // 128 * 68

    int tid = threadIdx.x;
    for (int i = tid; i < 2048; i += 128)
        ((float4*)s_w)[i] = ((const float4*)W_px)[i];
    if (tid < 64) { s_g[tid] = ln_g[tid]; s_b[tid] = ln_b[tid]; }

    int t = blockIdx.x * 128 + tid;
    const float* sh = g_SH + (size_t)t * Hq;
    float mean = 0.0f;
    for (int h = 0; h < Hq; h++) mean += sh[h];
    mean *= (1.0f / Hq);
    float var = 0.0f;
    for (int h = 0; h < Hq; h++) { float d = sh[h] - mean; var += d * d; }
    var *= (1.0f / Hq);
    float rstd = rsqrtf(var + 1e-6f);
    __syncthreads();

    float* tr = s_t + tid * 68;
    for (int h = 0; h < Hq; h++)
        tr[h] = (sh[h] - mean) * rstd * s_g[h] + s_b[h];

    float* outp = g_T + (size_t)t * 128;
    const float4* w4 = (const float4*)s_w;
    for (int jq = 0; jq < 32; jq++) {
        float4 acc = __ldg((const float4*)b_px + jq);
#pragma unroll 4
        for (int h4 = 0; h4 < 16; h4++) {
            float4 iv = *(const float4*)(tr + h4 * 4);
            float4 w;
            w = w4[(h4 * 4 + 0) * 32 + jq];
            acc.x += iv.x * w.x; acc.y += iv.x * w.y; acc.z += iv.x * w.z; acc.w += iv.x * w.w;
            w = w4[(h4 * 4 + 1) * 32 + jq];
            acc.x += iv.y * w.x; acc.y += iv.y * w.y; acc.z += iv.y * w.z; acc.w += iv.y * w.w;
            w = w4[(h4 * 4 + 2) * 32 + jq];
            acc.x += iv.z * w.x; acc.y += iv.z * w.y; acc.z += iv.z * w.z; acc.w += iv.z * w.w;
            w = w4[(h4 * 4 + 3) * 32 + jq];
            acc.x += iv.w * w.x; acc.y += iv.w * w.y; acc.z += iv.w * w.z; acc.w += iv.w * w.w;
        }
        ((float4*)outp)[jq] = acc;
    }
}

// ---------------- row matvec helper [R1] ----------------
__device__ __forceinline__ float4 mm_row(const float* __restrict__ in,
                                         const float* __restrict__ wsm, int jq) {
    const float4* w4 = (const float4*)wsm;
    float4 acc = make_float4(0.f, 0.f, 0.f, 0.f);
#pragma unroll 4
    for (int h4 = 0; h4 < 16; h4++) {
        float4 iv = *(const float4*)(in + h4 * 4);
        float4 w;
        w = w4[(h4 * 4 + 0) * 16 + jq];
        acc.x += iv.x * w.x; acc.y += iv.x * w.y; acc.z += iv.x * w.z; acc.w += iv.x * w.w;
        w = w4[(h4 * 4 + 1) * 16 + jq];
        acc.x += iv.y * w.x; acc.y += iv.y * w.y; acc.z += iv.y * w.z; acc.w += iv.y * w.w;
        w = w4[(h4 * 4 + 2) * 16 + jq];
        acc.x += iv.z * w.x; acc.y += iv.z * w.y; acc.z += iv.z * w.z; acc.w += iv.z * w.w;
        w = w4[(h4 * 4 + 3) * 16 + jq];
        acc.x += iv.w * w.x; acc.y += iv.w * w.y; acc.z += iv.w * w.z; acc.w += iv.w * w.w;
    }
    return acc;
}

// ---------------- K5: conv + GLU + matmul chain [R1 version] ----------------
__global__ void __launch_bounds__(128) k_post(
    const float* __restrict__ conv_sh,
    const float* __restrict__ W_pxx,    const float* __restrict__ b_pxx,
    const float* __restrict__ W_dte,    const float* __restrict__ b_dte,
    const float* __restrict__ W_dteall, const float* __restrict__ b_dteall,
    const float* __restrict__ W_fmod,   const float* __restrict__ b_fmod,
    const float* __restrict__ W_fx,     const float* __restrict__ b_fx,
    const float* __restrict__ W_fxx,    const float* __restrict__ b_fxx,
    float* __restrict__ d_out) {
    extern __shared__ float sm[];
    float* s_pxx    = sm;
    float* s_dte    = sm + 4096;
    float* s_dteall = sm + 8192;
    float* s_fmod   = sm + 12288;
    float* s_fx     = sm + 16384;
    float* s_fxx    = sm + 20480;
    float* s_cv     = sm + 24576;
    float* sA       = sm + 25152;
    float* sB       = sm + 25152 + 8704;
    float* sC       = sm + 25152 + 2 * 8704;

    int tid = threadIdx.x;
    {
        const float* wsrc[6] = {W_pxx, W_dte, W_dteall, W_fmod, W_fx, W_fxx};
#pragma unroll
        for (int m = 0; m < 6; m++)
            for (int i = tid; i < 1024; i += 128)
                ((float4*)(sm + m * 4096))[i] = ((const float4*)wsrc[m])[i];
        for (int i = tid; i < 576; i += 128) {
            int tap = i >> 6, h = i & 63;
            s_cv[i] = conv_sh[h * 9 + tap];
        }
    }
    __syncthreads();

    int t = blockIdx.x * 128 + tid;
    int l = t & 255, ii = l >> 4, jj = l & 15;
    float* rA = sA + tid * 68;
    float* rB = sB + tid * 68;
    float* rC = sC + tid * 68;
    const float* Trow = g_T + (size_t)t * 128;

    for (int q = 0; q < 16; q++) {
        float4 acc = make_float4(0.f, 0.f, 0.f, 0.f);
#pragma unroll
        for (int tap = 0; tap < 9; tap++) {
            int di = tap / 3 - 1, dj = tap % 3 - 1;
            int ni = ii + di, nj = jj + dj;
            if (ni < 0 || ni > 15 || nj < 0 || nj > 15) continue;
            float4 v = *(const float4*)(g_T + (size_t)(t + di * 16 + dj) * 128 + q * 4);
            float4 w = *(const float4*)(s_cv + tap * 64 + q * 4);
            acc = f4add(acc, f4mul(v, w));
        }
        float4 t2 = *(const float4*)(Trow + 64 + q * 4);
        *(float4*)(rA + q * 4) = f4mul(gelu4(acc), t2);
    }

    for (int q = 0; q < 16; q++) {
        float4 acc = mm_row(rA, s_pxx, q);
        acc = f4add(acc, __ldg((const float4*)b_pxx + q));
        acc = f4add(acc, *(const float4*)(g_SH + (size_t)t * 64 + q * 4));
        *(float4*)(rB + q * 4) = acc;
    }

    for (int q = 0; q < 16; q++)
        *(float4*)(rC + q * 4) = *(const float4*)(g_Y + (size_t)t * 64 + q * 4);

    for (int q = 0; q < 16; q++) {
        float4 acc = mm_row(rC, s_dte, q);
        acc = f4add(acc, mm_row(rB, s_dteall, q));
        acc = f4add(acc, __ldg((const float4*)b_dte + q));
        acc = f4add(acc, __ldg((const float4*)b_dteall + q));
        *(float4*)(rA + q * 4) = gelu4(acc);
    }

    for (int q = 0; q < 16; q++) {
        float4 acc = mm_row(rA, s_fmod, q);
        acc = f4add(acc, __ldg((const float4*)b_fmod + q));
        *(float4*)(rB + q * 4) = gelu4(acc);
    }

    for (int q = 0; q < 16; q++)
        *(float4*)(rC + q * 4) =
            gelu4(*(const float4*)(g_RGB + (size_t)t * 64 + q * 4));

    for (int q = 0; q < 16; q++) {
        float4 a = mm_row(rC, s_fx, q);
        a = f4add(a, __ldg((const float4*)b_fx + q));
        float4 gm = *(const float4*)(rB + q * 4);
        *(float4*)(rB + q * 4) = f4mul(gm, a);
    }

    for (int q = 0; q < 16; q++) {
        float4 acc = mm_row(rB, s_fxx, q);
        acc = f4add(acc, __ldg((const float4*)b_fxx + q));
        acc = f4add(acc, *(const float4*)(g_RGB + (size_t)t * 64 + q * 4));
        *(float4*)(d_out + (size_t)t * 64 + q * 4) = acc;
    }
}

// ---------------- host launcher ----------------
extern "C" void kernel_launch(void* const* d_in, const int* in_sizes, int n_in,
                              void* d_out, int out_size) {
    const float* x        = (const float*)d_in[0];
    const float* dte      = (const float*)d_in[1];
    const float* w_gate   = (const float*)d_in[2];
    const float* W_exp    = (const float*)d_in[3];
    const float* b_exp    = (const float*)d_in[4];
    const float* W_sh     = (const float*)d_in[5];
    const float* b_sh     = (const float*)d_in[6];
    const float* ln_g     = (const float*)d_in[7];
    const float* ln_b     = (const float*)d_in[8];
    const float* W_px     = (const float*)d_in[9];
    const float* b_px     = (const float*)d_in[10];
    const float* conv_sh  = (const float*)d_in[11];
    const float* W_pxx    = (const float*)d_in[12];
    const float* b_pxx    = (const float*)d_in[13];
    const float* W_dte    = (const float*)d_in[14];
    const float* b_dte    = (const float*)d_in[15];
    const float* W_dteall = (const float*)d_in[16];
    const float* b_dteall = (const float*)d_in[17];
    const float* W_rgb    = (const float*)d_in[18];
    const float* b_rgb    = (const float*)d_in[19];
    const float* W_fx     = (const float*)d_in[20];
    const float* b_fx     = (const float*)d_in[21];
    const float* W_fmod   = (const float*)d_in[22];
    const float* b_fmod   = (const float*)d_in[23];
    const float* W_fxx    = (const float*)d_in[24];
    const float* b_fxx    = (const float*)d_in[25];
    float* out = (float*)d_out;

    cudaFuncSetAttribute(k_gemm_mma, cudaFuncAttributeMaxDynamicSharedMemorySize, SMEM_MM);
    cudaFuncSetAttribute(k_preln, cudaFuncAttributeMaxDynamicSharedMemorySize, 68096);
    cudaFuncSetAttribute(k_post,  cudaFuncAttributeMaxDynamicSharedMemorySize, 205056);

    k_mean<<<NT / 8, 256>>>(dte);
    k_gate<<<1, 64>>>(w_gate, b_exp, out, out_size - 1);

    k_gemm_mma<<<256, 256, SMEM_MM>>>(dte, x, W_exp, W_sh, b_sh, W_rgb, b_rgb);

    k_preln<<<128, 128, 68096>>>(W_px, b_px, ln_g, ln_b);
    k_post<<<128, 128, 205056>>>(conv_sh,
                                 W_pxx, b_pxx, W_dte, b_dte, W_dteall, b_dteall,
                                 W_fmod, b_fmod, W_fx, b_fx, W_fxx, b_fxx,
                                 out);
}